// round 16
// baseline (speedup 1.0000x reference)
#include <cuda_runtime.h>
#include <cuda_bf16.h>
#include <cstdint>

// WCT folded: out = A_b * x + bias_b, A_b = alpha*I + (1-alpha)*M_b,
// M_b = cov_{perm[b]}^{1/2} * cov_b^{-1/2} via coupled Newton-Schulz.
// R15: ns+comb fused into nsc_kernel (2 NS instances per block, M/A/bias
//      in-block); packed bf16x2 cvt + f32x2 channel sums in staging.
//      gram/apply structure = the verified 350us configuration.

#define BATCH 16
#define HW 65536
#define NCH 64
#define GBLK 32
#define GPIX (HW / GBLK)        // 2048
#define NS_ITERS 5
#define MS 68

// apply config
#define ABLKS 16
#define APB   4096
#define ATL   128
#define NTIL  (APB / ATL)       // 32
#define XROW  72
#define AROW  72

// gram config
#define GXROW 72
#define GNT   (GPIX / 128)      // 16 staged tiles per block

// ---- device scratch ----
__device__ float g_part[BATCH][GBLK][NCH * NCH];
__device__ float g_psum[BATCH][GBLK][NCH];
__device__ float g_A  [BATCH][NCH * NCH];          // row-major: g_A[c*64+k]
__device__ float g_bias[BATCH][NCH];

// ---- packed f32x2 helpers ----
__device__ __forceinline__ void ffma2(unsigned long long& d,
                                      unsigned long long a,
                                      unsigned long long b) {
    asm("fma.rn.f32x2 %0, %1, %2, %0;" : "+l"(d) : "l"(a), "l"(b));
}
__device__ __forceinline__ unsigned long long fadd2(unsigned long long a,
                                                    unsigned long long b) {
    unsigned long long r;
    asm("add.rn.f32x2 %0, %1, %2;" : "=l"(r) : "l"(a), "l"(b));
    return r;
}
__device__ __forceinline__ unsigned long long dup2f(float v) {
    unsigned long long r;
    unsigned u = __float_as_uint(v);
    asm("mov.b64 %0, {%1, %1};" : "=l"(r) : "r"(u));
    return r;
}
__device__ __forceinline__ unsigned long long pack2f(float a, float b) {
    unsigned long long r;
    asm("mov.b64 %0, {%1, %2};" : "=l"(r)
        : "r"(__float_as_uint(a)), "r"(__float_as_uint(b)));
    return r;
}
__device__ __forceinline__ float lo32(unsigned long long v) {
    return __uint_as_float((unsigned)v);
}
__device__ __forceinline__ float hi32(unsigned long long v) {
    return __uint_as_float((unsigned)(v >> 32));
}

// ---- warp mma helpers ----
__device__ __forceinline__ uint32_t smem_u32(const void* p) {
    return (uint32_t)__cvta_generic_to_shared(p);
}
__device__ __forceinline__ void ldm4(uint32_t r[4], uint32_t addr) {
    asm volatile("ldmatrix.sync.aligned.m8n8.x4.shared.b16 {%0,%1,%2,%3}, [%4];"
                 : "=r"(r[0]), "=r"(r[1]), "=r"(r[2]), "=r"(r[3]) : "r"(addr));
}
__device__ __forceinline__ void ldm4t(uint32_t r[4], uint32_t addr) {
    asm volatile("ldmatrix.sync.aligned.m8n8.x4.trans.shared.b16 {%0,%1,%2,%3}, [%4];"
                 : "=r"(r[0]), "=r"(r[1]), "=r"(r[2]), "=r"(r[3]) : "r"(addr));
}
__device__ __forceinline__ void mma_bf16(float c[4], const uint32_t a[4],
                                         const uint32_t b0, const uint32_t b1) {
    asm volatile(
        "mma.sync.aligned.m16n8k16.row.col.f32.bf16.bf16.f32 "
        "{%0,%1,%2,%3}, {%4,%5,%6,%7}, {%8,%9}, {%0,%1,%2,%3};"
        : "+f"(c[0]), "+f"(c[1]), "+f"(c[2]), "+f"(c[3])
        : "r"(a[0]), "r"(a[1]), "r"(a[2]), "r"(a[3]), "r"(b0), "r"(b1));
}
__device__ __forceinline__ uint32_t bf2bits(__nv_bfloat162 v) {
    return *reinterpret_cast<uint32_t*>(&v);
}

// upper-triangle m16n8 tile list: 20 tiles (mi 0..3, nj >= 2*mi)
__device__ __forceinline__ int gmi(int ti) {
    return (ti >= 8) + (ti >= 14) + (ti >= 18);
}
__device__ __forceinline__ int gnj(int ti) {
    int mi = gmi(ti);
    return ti - (mi >= 1) * 6 - (mi >= 2) * 4 - (mi >= 3) * 2;
}

// ============================================================================
// Kernel 1: Gram + channel sums via mma.sync. grid (GBLK, BATCH), 256 threads.
// Prefetch-first ordering; packed bf16x2 cvt + f32x2 channel sums.
// ============================================================================
__device__ __forceinline__ void g_load(float4 pf[8], const float4* __restrict__ src,
                                       int tid) {
#pragma unroll
    for (int r = 0; r < 8; ++r) pf[r] = src[tid + 256 * r];
}
__device__ __forceinline__ void g_store(unsigned short* hx, const float4 pf[8],
                                        int tid, unsigned long long s2[2]) {
#pragma unroll
    for (int r = 0; r < 8; ++r) {
        const int f = tid + 256 * r;
        const float4 v = pf[r];
        const int px = f >> 4, k0 = (f & 15) * 4;
        __nv_bfloat162 h01 = __float22bfloat162_rn(make_float2(v.x, v.y));
        __nv_bfloat162 h23 = __float22bfloat162_rn(make_float2(v.z, v.w));
        uint2 hp;
        hp.x = bf2bits(h01);
        hp.y = bf2bits(h23);
        *reinterpret_cast<uint2*>(hx + px * GXROW + k0) = hp;
        s2[0] = fadd2(s2[0], pack2f(v.x, v.y));
        s2[1] = fadd2(s2[1], pack2f(v.z, v.w));
    }
}

__global__ void __launch_bounds__(256) gram_mma_kernel(const float* __restrict__ x) {
    extern __shared__ char gsm[];
    unsigned short* XH[2] = {(unsigned short*)gsm,
                             (unsigned short*)(gsm + 18432)};
    __shared__ float ssum[256][4];

    const int tid = threadIdx.x, w = tid >> 5, lane = tid & 31;
    const int b = blockIdx.y, blk = blockIdx.x;

    const float4* x4 = reinterpret_cast<const float4*>(x) +
                       ((size_t)b * HW + (size_t)blk * GPIX) * (NCH / 4);

    unsigned long long s2[2] = {0ull, 0ull};
    float C[20][4];
#pragma unroll
    for (int ti = 0; ti < 20; ++ti)
#pragma unroll
        for (int q = 0; q < 4; ++q) C[ti][q] = 0.f;

    float4 pf[8];
    g_load(pf, x4, tid);
    g_store(XH[0], pf, tid, s2);
    __syncthreads();

    const int kb = w * 16;
    const int krow_a = (lane & 7) + ((lane >> 4) << 3);
    const int mcol_a = ((lane >> 3) & 1) << 3;
    const int krow_b = (lane & 7) + (((lane >> 3) & 1) << 3);
    const int ncol_b = (lane >> 4) << 3;

    for (int t = 0; t < GNT; ++t) {
        const int cb = t & 1;
        if (t + 1 < GNT) g_load(pf, x4 + (size_t)(t + 1) * 2048, tid);

        const uint32_t xs = smem_u32(XH[cb]);
        uint32_t ah[4][4];
#pragma unroll
        for (int mi = 0; mi < 4; ++mi)
            ldm4t(ah[mi], xs + (uint32_t)(((kb + krow_a) * GXROW +
                                           mi * 16 + mcol_a) * 2));
        uint32_t bh[8][2];
#pragma unroll
        for (int p = 0; p < 4; ++p) {
            uint32_t r[4];
            ldm4t(r, xs + (uint32_t)(((kb + krow_b) * GXROW +
                                      p * 16 + ncol_b) * 2));
            bh[2 * p][0] = r[0];     bh[2 * p][1] = r[1];
            bh[2 * p + 1][0] = r[2]; bh[2 * p + 1][1] = r[3];
        }
#pragma unroll
        for (int ti = 0; ti < 20; ++ti)
            mma_bf16(C[ti], ah[gmi(ti)], bh[gnj(ti)][0], bh[gnj(ti)][1]);
        __syncthreads();

        if (t + 1 < GNT) {
            g_store(XH[cb ^ 1], pf, tid, s2);
            __syncthreads();
        }
    }

    // channel sums (f32-exact means)
    ssum[tid][0] = lo32(s2[0]); ssum[tid][1] = hi32(s2[0]);
    ssum[tid][2] = lo32(s2[1]); ssum[tid][3] = hi32(s2[1]);
    __syncthreads();
    if (tid < 64) {
        float s = 0.f;
#pragma unroll
        for (int g = 0; g < 16; ++g) s += ssum[g * 16 + (tid >> 2)][tid & 3];
        g_psum[b][blk][tid] = s;
    }

    // cross-warp reduce of C, 4 tiles per round; mirror writeout (i<=j rule)
    float* scr = (float*)gsm;
    for (int round = 0; round < 5; ++round) {
        __syncthreads();
#pragma unroll
        for (int rt = 0; rt < 4; ++rt) {
            const int ti = round * 4 + rt;
            float* dst = scr + ((rt * 8 + w) * 32 + lane) * 4;
            dst[0] = C[ti][0]; dst[1] = C[ti][1];
            dst[2] = C[ti][2]; dst[3] = C[ti][3];
        }
        __syncthreads();
        for (int e = tid; e < 512; e += 256) {
            const int rt = e >> 7, idx = e & 127, ln = idx >> 2, q = idx & 3;
            const int ti = round * 4 + rt;
            float v = 0.f;
#pragma unroll
            for (int ww = 0; ww < 8; ++ww)
                v += scr[((rt * 8 + ww) * 32 + ln) * 4 + q];
            const int i = gmi(ti) * 16 + (ln >> 2) + ((q >> 1) << 3);
            const int j = gnj(ti) * 8 + (ln & 3) * 2 + (q & 1);
            if (i <= j) {
                g_part[b][blk][i * 64 + j] = v;
                g_part[b][blk][j * 64 + i] = v;
            }
        }
    }
}

// ============================================================================
// 64x64 smem matmul helpers (stride MS), packed f32x2.
// ============================================================================
__device__ __forceinline__ void mm64p(const float* __restrict__ A,
                                      const float* __restrict__ B,
                                      unsigned long long r2[8], int i, int j0) {
#pragma unroll
    for (int q = 0; q < 8; q++) r2[q] = 0ull;
#pragma unroll 8
    for (int k = 0; k < 64; ++k) {
        unsigned long long ad = dup2f(A[i * MS + k]);
        const ulonglong2* b2 = reinterpret_cast<const ulonglong2*>(B + k * MS + j0);
        ulonglong2 x0 = b2[0], x1 = b2[1], x2 = b2[2], x3 = b2[3];
        ffma2(r2[0], ad, x0.x); ffma2(r2[1], ad, x0.y);
        ffma2(r2[2], ad, x1.x); ffma2(r2[3], ad, x1.y);
        ffma2(r2[4], ad, x2.x); ffma2(r2[5], ad, x2.y);
        ffma2(r2[6], ad, x3.x); ffma2(r2[7], ad, x3.y);
    }
}

__device__ __forceinline__ void mm64p8(const float* __restrict__ A,
                                       const float* __restrict__ B,
                                       unsigned long long r2[4], int i, int j0) {
#pragma unroll
    for (int q = 0; q < 4; q++) r2[q] = 0ull;
#pragma unroll 8
    for (int k = 0; k < 64; ++k) {
        unsigned long long ad = dup2f(A[i * MS + k]);
        const ulonglong2* b2 = reinterpret_cast<const ulonglong2*>(B + k * MS + j0);
        ulonglong2 x0 = b2[0], x1 = b2[1];
        ffma2(r2[0], ad, x0.x); ffma2(r2[1], ad, x0.y);
        ffma2(r2[2], ad, x1.x); ffma2(r2[3], ad, x1.y);
    }
}

__device__ __forceinline__ void mm64p4(const float* __restrict__ A,
                                       const float* __restrict__ B,
                                       unsigned long long r2[2], int i, int j0) {
    r2[0] = 0ull; r2[1] = 0ull;
#pragma unroll 8
    for (int k = 0; k < 64; ++k) {
        unsigned long long ad = dup2f(A[i * MS + k]);
        const ulonglong2* b2 = reinterpret_cast<const ulonglong2*>(B + k * MS + j0);
        ulonglong2 x0 = b2[0];
        ffma2(r2[0], ad, x0.x); ffma2(r2[1], ad, x0.y);
    }
}

// ============================================================================
// Kernel 2 (fused ns+comb): grid BATCH, 1024 threads.
// side 0 (tid<512): NS of cov_{perm[b]} -> Y0. side 1: NS of cov_b -> Z1.
// Then M = sqrt(c0)/sqrt(c1) * Y0*Z1; A = al*I + oma*M; bias in-block.
// Dynamic smem: 6 * 64 * MS floats (104448 B).
// ============================================================================
__global__ void __launch_bounds__(1024) nsc_kernel(const int* __restrict__ perm,
                                                   const float* __restrict__ alpha) {
    extern __shared__ float dsm[];
    __shared__ float mean2[2][NCH];
    __shared__ float red[1024];
    __shared__ float cnorm[2];

    const int b = blockIdx.x, tid = threadIdx.x;
    const int side = tid >> 9;          // 0: perm[b] (Y), 1: b (Z)
    const int u = tid & 511;
    const int pb = perm[b];
    const int mb = side ? b : pb;

    float* sY = dsm + side * 3 * 64 * MS;
    float* sZ = sY + 64 * MS;
    float* sT = sZ + 64 * MS;

    // means (per side, its own matrix)
    if (u < NCH) {
        float s = 0.f;
#pragma unroll
        for (int k = 0; k < GBLK; ++k) s += g_psum[mb][k][u];
        mean2[side][u] = s * (1.f / (float)HW);
    }
    __syncthreads();

    // cov reduce into sZ (temp)
    const float inv_d = 1.f / (float)(HW - 1);
    for (int e = u; e < 4096; e += 512) {
        float s = 0.f;
#pragma unroll
        for (int k = 0; k < GBLK; ++k) s += g_part[mb][k][e];
        int i = e >> 6, j = e & 63;
        sZ[i * MS + j] = (s - (float)HW * mean2[side][i] * mean2[side][j]) * inv_d;
    }
    __syncthreads();

    // infinity norm
    if (u < 64) {
        float s = 0.f;
        for (int j = 0; j < 64; ++j) s += fabsf(sZ[u * MS + j]);
        sY[u] = s;
    }
    __syncthreads();
    if (u == 0) {
        float m = 0.f;
        for (int r = 0; r < 64; ++r) m = fmaxf(m, sY[r]);
        cnorm[side] = m;
    }
    __syncthreads();
    const float c = cnorm[side];
    const float inv_c = 1.f / c;
    __syncthreads();

    for (int e = u; e < 4096; e += 512) {
        int r = e >> 6, q = e & 63;
        float v = sZ[r * MS + q];
        sY[r * MS + q] = v * inv_c;
        sZ[r * MS + q] = (r == q) ? 1.f : 0.f;
    }
    __syncthreads();

    const int i8 = u >> 3, j8 = (u & 7) * 8;
    const int u2 = u & 255;
    const int i16 = u2 >> 2, j16 = (u2 & 3) * 16;

    for (int it = 0; it < NS_ITERS; ++it) {
        // T = 1.5 I - 0.5 * Z*Y  (512 threads per side, 8-wide)
        unsigned long long t2[4];
        mm64p8(sZ, sY, t2, i8, j8);
#pragma unroll
        for (int q = 0; q < 4; q++) {
            int j = j8 + 2 * q;
            sT[i8 * MS + j]     = ((i8 == j)     ? 1.5f : 0.f) - 0.5f * lo32(t2[q]);
            sT[i8 * MS + j + 1] = ((i8 == j + 1) ? 1.5f : 0.f) - 0.5f * hi32(t2[q]);
        }
        __syncthreads();

        // Y' = Y*T (u<256), Z' = T*Z (u>=256), 16-wide
        unsigned long long r2[8];
        if (u < 256) mm64p(sY, sT, r2, i16, j16);
        else         mm64p(sT, sZ, r2, i16, j16);
        __syncthreads();
        float* dst = (u < 256) ? sY : sZ;
#pragma unroll
        for (int q = 0; q < 8; q++) {
            dst[i16 * MS + j16 + 2 * q]     = lo32(r2[q]);
            dst[i16 * MS + j16 + 2 * q + 1] = hi32(r2[q]);
        }
        __syncthreads();
    }

    // M = sscale * Y0 * Z1 ; A = al*I + oma*M ; bias = oma*(mean_pb - M*mean_b)
    const float* Y0 = dsm;                       // side 0 sY
    const float* Z1 = dsm + 3 * 64 * MS + 64 * MS;   // side 1 sZ
    const float sscale = sqrtf(cnorm[0]) * rsqrtf(cnorm[1]);
    const float al = alpha[b];
    const float oma = 1.f - al;

    const int i4 = tid >> 4, j4 = (tid & 15) * 4;
    unsigned long long m2[2];
    mm64p4(Y0, Z1, m2, i4, j4);
    float m[4] = {lo32(m2[0]), hi32(m2[0]), lo32(m2[1]), hi32(m2[1])};

    float pdot = 0.f;
#pragma unroll
    for (int q = 0; q < 4; q++) {
        const int j = j4 + q;
        const float Msc = sscale * m[q];
        g_A[b][i4 * 64 + j] = ((i4 == j) ? al : 0.f) + oma * Msc;
        pdot += Msc * mean2[1][j];
    }
    red[tid] = pdot;
    __syncthreads();
    if (tid < 64) {
        float dot = 0.f;
#pragma unroll
        for (int t = 0; t < 16; t++) dot += red[tid * 16 + t];
        g_bias[b][tid] = oma * (mean2[0][tid] - dot);
    }
}

// ============================================================================
// Kernel 3: out = A*x + bias via mma.sync bf16 split (verified 133us kernel;
// only change: packed bf16x2 cvt in staging, numerics-identical).
// grid (ABLKS, BATCH), 256 threads, 2 blocks/SM pinned.
// ============================================================================
#define SM_HX0  0
#define SM_HX1  18432
#define SM_LX0  36864
#define SM_LX1  55296
#define SM_AH   73728
#define SM_AL   82944
#define SM_BIAS 92160
#define APPLY_SMEM (SM_BIAS + 256)

__device__ __forceinline__ void stage_tile(unsigned short* hx, unsigned short* lx,
                                           const float4* __restrict__ src, int tid) {
#pragma unroll
    for (int r = 0; r < 8; ++r) {
        const int f = tid + 256 * r;
        const float4 v = src[f];
        const int px = f >> 4, k0 = (f & 15) * 4;
        __nv_bfloat162 h01 = __float22bfloat162_rn(make_float2(v.x, v.y));
        __nv_bfloat162 h23 = __float22bfloat162_rn(make_float2(v.z, v.w));
        float2 f01 = __bfloat1622float2(h01);
        float2 f23 = __bfloat1622float2(h23);
        __nv_bfloat162 l01 = __float22bfloat162_rn(make_float2(v.x - f01.x, v.y - f01.y));
        __nv_bfloat162 l23 = __float22bfloat162_rn(make_float2(v.z - f23.x, v.w - f23.y));
        uint2 hp, lp;
        hp.x = bf2bits(h01); hp.y = bf2bits(h23);
        lp.x = bf2bits(l01); lp.y = bf2bits(l23);
        *reinterpret_cast<uint2*>(hx + px * XROW + k0) = hp;
        *reinterpret_cast<uint2*>(lx + px * XROW + k0) = lp;
    }
}

__global__ void __launch_bounds__(256, 2) apply_mma_kernel(const float* __restrict__ x,
                                                           float* __restrict__ out) {
    extern __shared__ char smem[];
    unsigned short* HX[2] = {(unsigned short*)(smem + SM_HX0),
                             (unsigned short*)(smem + SM_HX1)};
    unsigned short* LX[2] = {(unsigned short*)(smem + SM_LX0),
                             (unsigned short*)(smem + SM_LX1)};
    unsigned short* AH = (unsigned short*)(smem + SM_AH);
    unsigned short* AL = (unsigned short*)(smem + SM_AL);
    float* sbias = (float*)(smem + SM_BIAS);

    const int tid = threadIdx.x;
    const int w = tid >> 5, lane = tid & 31;
    const int b = blockIdx.y, blk = blockIdx.x;

    for (int e = tid; e < 4096; e += 256) {
        const int c = e >> 6, k = e & 63;
        const float a = g_A[b][e];
        __nv_bfloat16 h = __float2bfloat16_rn(a);
        float rl = a - __bfloat162float(h);
        AH[c * AROW + k] = __bfloat16_as_ushort(h);
        AL[c * AROW + k] = __bfloat16_as_ushort(__float2bfloat16_rn(rl));
    }
    if (tid < 64) sbias[tid] = g_bias[b][tid];

    const float4* x4 = reinterpret_cast<const float4*>(x) +
                       ((size_t)b * HW + (size_t)blk * APB) * (NCH / 4);
    float* ob = out + ((size_t)b * HW + (size_t)blk * APB) * NCH;

    stage_tile(HX[0], LX[0], x4, tid);
    __syncthreads();

    const int pxb   = (w >> 1) * 32;
    const int nbase = (w & 1) * 32;
    uint32_t Bh[4][4][2], Bl[4][4][2];
    {
        const uint32_t ah_s = smem_u32(AH), al_s = smem_u32(AL);
        const int rown = nbase + (lane & 7) + ((lane >> 4) << 3);
        const int koff = ((lane >> 3) & 1) * 8;
#pragma unroll
        for (int ks = 0; ks < 4; ++ks)
#pragma unroll
            for (int ntp = 0; ntp < 2; ++ntp) {
                const uint32_t off =
                    (uint32_t)(((rown + ntp * 16) * AROW + ks * 16 + koff) * 2);
                uint32_t rh[4], rl[4];
                ldm4(rh, ah_s + off);
                ldm4(rl, al_s + off);
                Bh[ks][ntp * 2][0] = rh[0]; Bh[ks][ntp * 2][1] = rh[1];
                Bh[ks][ntp * 2 + 1][0] = rh[2]; Bh[ks][ntp * 2 + 1][1] = rh[3];
                Bl[ks][ntp * 2][0] = rl[0]; Bl[ks][ntp * 2][1] = rl[1];
                Bl[ks][ntp * 2 + 1][0] = rl[2]; Bl[ks][ntp * 2 + 1][1] = rl[3];
            }
    }

    float2 bv[4];
    {
        const int cpair = (lane & 3) * 2;
#pragma unroll
        for (int nt = 0; nt < 4; ++nt) {
            bv[nt].x = sbias[nbase + nt * 8 + cpair];
            bv[nt].y = sbias[nbase + nt * 8 + cpair + 1];
        }
    }

    const int xrow = (lane & 15);
    const int xkof = ((lane >> 4) << 3);

    for (int t = 0; t < NTIL; ++t) {
        const int cb = t & 1;

        if (t + 1 < NTIL)
            stage_tile(HX[cb ^ 1], LX[cb ^ 1], x4 + (size_t)(t + 1) * 2048, tid);

        const uint32_t hx_s = smem_u32(HX[cb]), lx_s = smem_u32(LX[cb]);

        float C[2][4][4];
#pragma unroll
        for (int mt = 0; mt < 2; ++mt)
#pragma unroll
            for (int nt = 0; nt < 4; ++nt)
#pragma unroll
                for (int q = 0; q < 4; ++q) C[mt][nt][q] = 0.f;

#pragma unroll
        for (int ks = 0; ks < 4; ++ks) {
            uint32_t ah[2][4], al[2][4];
#pragma unroll
            for (int mt = 0; mt < 2; ++mt) {
                const uint32_t off = (uint32_t)(
                    ((pxb + mt * 16 + xrow) * XROW + ks * 16 + xkof) * 2);
                ldm4(ah[mt], hx_s + off);
                ldm4(al[mt], lx_s + off);
            }
#pragma unroll
            for (int mt = 0; mt < 2; ++mt)
#pragma unroll
                for (int nt = 0; nt < 4; ++nt) {
                    mma_bf16(C[mt][nt], ah[mt], Bh[ks][nt][0], Bh[ks][nt][1]);
                    mma_bf16(C[mt][nt], al[mt], Bh[ks][nt][0], Bh[ks][nt][1]);
                    mma_bf16(C[mt][nt], ah[mt], Bl[ks][nt][0], Bl[ks][nt][1]);
                }
        }

        const int gr = lane >> 2, cpair = (lane & 3) * 2;
        const int pxg = t * ATL + pxb + gr;
#pragma unroll
        for (int mt = 0; mt < 2; ++mt) {
            float* row0 = ob + (size_t)(pxg + mt * 16) * NCH;
            float* row1 = row0 + 8 * NCH;
#pragma unroll
            for (int nt = 0; nt < 4; ++nt) {
                const int n = nbase + nt * 8 + cpair;
                *reinterpret_cast<float2*>(row0 + n) =
                    make_float2(C[mt][nt][0] + bv[nt].x, C[mt][nt][1] + bv[nt].y);
                *reinterpret_cast<float2*>(row1 + n) =
                    make_float2(C[mt][nt][2] + bv[nt].x, C[mt][nt][3] + bv[nt].y);
            }
        }
        __syncthreads();
    }
}

// ============================================================================
extern "C" void kernel_launch(void* const* d_in, const int* in_sizes, int n_in,
                              void* d_out, int out_size) {
    (void)in_sizes; (void)n_in; (void)out_size;
    const float* x     = (const float*)d_in[0];
    const int*   perm  = (const int*)d_in[1];
    const float* alpha = (const float*)d_in[2];
    float*       out   = (float*)d_out;

    const int nsc_smem  = 6 * 64 * MS * (int)sizeof(float);   // 104448 B
    const int gram_smem = 2 * 18432;                          // 36864 B
    cudaFuncSetAttribute(nsc_kernel, cudaFuncAttributeMaxDynamicSharedMemorySize,
                         nsc_smem);
    cudaFuncSetAttribute(apply_mma_kernel, cudaFuncAttributeMaxDynamicSharedMemorySize,
                         APPLY_SMEM);

    gram_mma_kernel<<<dim3(GBLK, BATCH), 256, gram_smem>>>(x);
    nsc_kernel<<<BATCH, 1024, nsc_smem>>>(perm, alpha);
    apply_mma_kernel<<<dim3(ABLKS, BATCH), 256, APPLY_SMEM>>>(x, out);
}

// round 17
// speedup vs baseline: 1.5063x; 1.5063x over previous
#include <cuda_runtime.h>
#include <cuda_bf16.h>
#include <cstdint>

// WCT folded: out = A_b * x + bias_b, A_b = alpha*I + (1-alpha)*M_b,
// M_b = cov_{perm[b]}^{1/2} * cov_b^{-1/2} via coupled Newton-Schulz.
// R17: revert R15's work-duplicating fusion -> separate ns+comb (R14
//      structure, shared g_half/g_invh across the permutation); keep
//      packed bf16x2 cvt staging; NS_ITERS 5->4 (residual 1.5e-9).

#define BATCH 16
#define HW 65536
#define NCH 64
#define GBLK 32
#define GPIX (HW / GBLK)        // 2048
#define NS_ITERS 4
#define MS 68

// apply config
#define ABLKS 16
#define APB   4096
#define ATL   128
#define NTIL  (APB / ATL)       // 32
#define XROW  72
#define AROW  72

// gram config
#define GXROW 72
#define GNT   (GPIX / 128)      // 16 staged tiles per block

// ---- device scratch ----
__device__ float g_part[BATCH][GBLK][NCH * NCH];
__device__ float g_psum[BATCH][GBLK][NCH];
__device__ float g_mean[BATCH][NCH];
__device__ float g_half[BATCH][NCH * NCH];
__device__ float g_invh[BATCH][NCH * NCH];
__device__ float g_A  [BATCH][NCH * NCH];          // row-major: g_A[c*64+k]
__device__ float g_bias[BATCH][NCH];

// ---- packed f32x2 helpers ----
__device__ __forceinline__ void ffma2(unsigned long long& d,
                                      unsigned long long a,
                                      unsigned long long b) {
    asm("fma.rn.f32x2 %0, %1, %2, %0;" : "+l"(d) : "l"(a), "l"(b));
}
__device__ __forceinline__ unsigned long long fadd2(unsigned long long a,
                                                    unsigned long long b) {
    unsigned long long r;
    asm("add.rn.f32x2 %0, %1, %2;" : "=l"(r) : "l"(a), "l"(b));
    return r;
}
__device__ __forceinline__ unsigned long long dup2f(float v) {
    unsigned long long r;
    unsigned u = __float_as_uint(v);
    asm("mov.b64 %0, {%1, %1};" : "=l"(r) : "r"(u));
    return r;
}
__device__ __forceinline__ unsigned long long pack2f(float a, float b) {
    unsigned long long r;
    asm("mov.b64 %0, {%1, %2};" : "=l"(r)
        : "r"(__float_as_uint(a)), "r"(__float_as_uint(b)));
    return r;
}
__device__ __forceinline__ float lo32(unsigned long long v) {
    return __uint_as_float((unsigned)v);
}
__device__ __forceinline__ float hi32(unsigned long long v) {
    return __uint_as_float((unsigned)(v >> 32));
}

// ---- warp mma helpers ----
__device__ __forceinline__ uint32_t smem_u32(const void* p) {
    return (uint32_t)__cvta_generic_to_shared(p);
}
__device__ __forceinline__ void ldm4(uint32_t r[4], uint32_t addr) {
    asm volatile("ldmatrix.sync.aligned.m8n8.x4.shared.b16 {%0,%1,%2,%3}, [%4];"
                 : "=r"(r[0]), "=r"(r[1]), "=r"(r[2]), "=r"(r[3]) : "r"(addr));
}
__device__ __forceinline__ void ldm4t(uint32_t r[4], uint32_t addr) {
    asm volatile("ldmatrix.sync.aligned.m8n8.x4.trans.shared.b16 {%0,%1,%2,%3}, [%4];"
                 : "=r"(r[0]), "=r"(r[1]), "=r"(r[2]), "=r"(r[3]) : "r"(addr));
}
__device__ __forceinline__ void mma_bf16(float c[4], const uint32_t a[4],
                                         const uint32_t b0, const uint32_t b1) {
    asm volatile(
        "mma.sync.aligned.m16n8k16.row.col.f32.bf16.bf16.f32 "
        "{%0,%1,%2,%3}, {%4,%5,%6,%7}, {%8,%9}, {%0,%1,%2,%3};"
        : "+f"(c[0]), "+f"(c[1]), "+f"(c[2]), "+f"(c[3])
        : "r"(a[0]), "r"(a[1]), "r"(a[2]), "r"(a[3]), "r"(b0), "r"(b1));
}
__device__ __forceinline__ uint32_t bf2bits(__nv_bfloat162 v) {
    return *reinterpret_cast<uint32_t*>(&v);
}

// upper-triangle m16n8 tile list: 20 tiles (mi 0..3, nj >= 2*mi)
__device__ __forceinline__ int gmi(int ti) {
    return (ti >= 8) + (ti >= 14) + (ti >= 18);
}
__device__ __forceinline__ int gnj(int ti) {
    int mi = gmi(ti);
    return ti - (mi >= 1) * 6 - (mi >= 2) * 4 - (mi >= 3) * 2;
}

// ============================================================================
// Kernel 1: Gram + channel sums via mma.sync. grid (GBLK, BATCH), 256 threads.
// Prefetch-first ordering; packed bf16x2 cvt + f32x2 channel sums.
// (Measured 78.3us in R15 profile.)
// ============================================================================
__device__ __forceinline__ void g_load(float4 pf[8], const float4* __restrict__ src,
                                       int tid) {
#pragma unroll
    for (int r = 0; r < 8; ++r) pf[r] = src[tid + 256 * r];
}
__device__ __forceinline__ void g_store(unsigned short* hx, const float4 pf[8],
                                        int tid, unsigned long long s2[2]) {
#pragma unroll
    for (int r = 0; r < 8; ++r) {
        const int f = tid + 256 * r;
        const float4 v = pf[r];
        const int px = f >> 4, k0 = (f & 15) * 4;
        __nv_bfloat162 h01 = __float22bfloat162_rn(make_float2(v.x, v.y));
        __nv_bfloat162 h23 = __float22bfloat162_rn(make_float2(v.z, v.w));
        uint2 hp;
        hp.x = bf2bits(h01);
        hp.y = bf2bits(h23);
        *reinterpret_cast<uint2*>(hx + px * GXROW + k0) = hp;
        s2[0] = fadd2(s2[0], pack2f(v.x, v.y));
        s2[1] = fadd2(s2[1], pack2f(v.z, v.w));
    }
}

__global__ void __launch_bounds__(256) gram_mma_kernel(const float* __restrict__ x) {
    extern __shared__ char gsm[];
    unsigned short* XH[2] = {(unsigned short*)gsm,
                             (unsigned short*)(gsm + 18432)};
    __shared__ float ssum[256][4];

    const int tid = threadIdx.x, w = tid >> 5, lane = tid & 31;
    const int b = blockIdx.y, blk = blockIdx.x;

    const float4* x4 = reinterpret_cast<const float4*>(x) +
                       ((size_t)b * HW + (size_t)blk * GPIX) * (NCH / 4);

    unsigned long long s2[2] = {0ull, 0ull};
    float C[20][4];
#pragma unroll
    for (int ti = 0; ti < 20; ++ti)
#pragma unroll
        for (int q = 0; q < 4; ++q) C[ti][q] = 0.f;

    float4 pf[8];
    g_load(pf, x4, tid);
    g_store(XH[0], pf, tid, s2);
    __syncthreads();

    const int kb = w * 16;
    const int krow_a = (lane & 7) + ((lane >> 4) << 3);
    const int mcol_a = ((lane >> 3) & 1) << 3;
    const int krow_b = (lane & 7) + (((lane >> 3) & 1) << 3);
    const int ncol_b = (lane >> 4) << 3;

    for (int t = 0; t < GNT; ++t) {
        const int cb = t & 1;
        if (t + 1 < GNT) g_load(pf, x4 + (size_t)(t + 1) * 2048, tid);

        const uint32_t xs = smem_u32(XH[cb]);
        uint32_t ah[4][4];
#pragma unroll
        for (int mi = 0; mi < 4; ++mi)
            ldm4t(ah[mi], xs + (uint32_t)(((kb + krow_a) * GXROW +
                                           mi * 16 + mcol_a) * 2));
        uint32_t bh[8][2];
#pragma unroll
        for (int p = 0; p < 4; ++p) {
            uint32_t r[4];
            ldm4t(r, xs + (uint32_t)(((kb + krow_b) * GXROW +
                                      p * 16 + ncol_b) * 2));
            bh[2 * p][0] = r[0];     bh[2 * p][1] = r[1];
            bh[2 * p + 1][0] = r[2]; bh[2 * p + 1][1] = r[3];
        }
#pragma unroll
        for (int ti = 0; ti < 20; ++ti)
            mma_bf16(C[ti], ah[gmi(ti)], bh[gnj(ti)][0], bh[gnj(ti)][1]);
        __syncthreads();

        if (t + 1 < GNT) {
            g_store(XH[cb ^ 1], pf, tid, s2);
            __syncthreads();
        }
    }

    // channel sums (f32-exact means)
    ssum[tid][0] = lo32(s2[0]); ssum[tid][1] = hi32(s2[0]);
    ssum[tid][2] = lo32(s2[1]); ssum[tid][3] = hi32(s2[1]);
    __syncthreads();
    if (tid < 64) {
        float s = 0.f;
#pragma unroll
        for (int g = 0; g < 16; ++g) s += ssum[g * 16 + (tid >> 2)][tid & 3];
        g_psum[b][blk][tid] = s;
    }

    // cross-warp reduce of C, 4 tiles per round; mirror writeout (i<=j rule)
    float* scr = (float*)gsm;
    for (int round = 0; round < 5; ++round) {
        __syncthreads();
#pragma unroll
        for (int rt = 0; rt < 4; ++rt) {
            const int ti = round * 4 + rt;
            float* dst = scr + ((rt * 8 + w) * 32 + lane) * 4;
            dst[0] = C[ti][0]; dst[1] = C[ti][1];
            dst[2] = C[ti][2]; dst[3] = C[ti][3];
        }
        __syncthreads();
        for (int e = tid; e < 512; e += 256) {
            const int rt = e >> 7, idx = e & 127, ln = idx >> 2, q = idx & 3;
            const int ti = round * 4 + rt;
            float v = 0.f;
#pragma unroll
            for (int ww = 0; ww < 8; ++ww)
                v += scr[((rt * 8 + ww) * 32 + ln) * 4 + q];
            const int i = gmi(ti) * 16 + (ln >> 2) + ((q >> 1) << 3);
            const int j = gnj(ti) * 8 + (ln & 3) * 2 + (q & 1);
            if (i <= j) {
                g_part[b][blk][i * 64 + j] = v;
                g_part[b][blk][j * 64 + i] = v;
            }
        }
    }
}

// ============================================================================
// 64x64 smem matmul helpers (stride MS), packed f32x2.
// ============================================================================
__device__ __forceinline__ void mm64p8(const float* __restrict__ A,
                                       const float* __restrict__ B,
                                       unsigned long long r2[4], int i, int j0) {
#pragma unroll
    for (int q = 0; q < 4; q++) r2[q] = 0ull;
#pragma unroll 8
    for (int k = 0; k < 64; ++k) {
        unsigned long long ad = dup2f(A[i * MS + k]);
        const ulonglong2* b2 = reinterpret_cast<const ulonglong2*>(B + k * MS + j0);
        ulonglong2 x0 = b2[0], x1 = b2[1];
        ffma2(r2[0], ad, x0.x); ffma2(r2[1], ad, x0.y);
        ffma2(r2[2], ad, x1.x); ffma2(r2[3], ad, x1.y);
    }
}

__device__ __forceinline__ void mm64p4(const float* __restrict__ A,
                                       const float* __restrict__ B,
                                       unsigned long long r2[2], int i, int j0) {
    r2[0] = 0ull; r2[1] = 0ull;
#pragma unroll 8
    for (int k = 0; k < 64; ++k) {
        unsigned long long ad = dup2f(A[i * MS + k]);
        const ulonglong2* b2 = reinterpret_cast<const ulonglong2*>(B + k * MS + j0);
        ulonglong2 x0 = b2[0];
        ffma2(r2[0], ad, x0.x); ffma2(r2[1], ad, x0.y);
    }
}

// ============================================================================
// Kernel 2: fused cov-reduction + Newton-Schulz. grid BATCH, 1024 threads.
// (R14 version, NS_ITERS=4.)
// ============================================================================
__global__ void __launch_bounds__(1024) ns_kernel() {
    extern __shared__ float dsm[];
    float* sY = dsm;
    float* sZ = sY + 64 * MS;
    float* sT = sZ + 64 * MS;
    __shared__ float mean_s[NCH];

    const int b = blockIdx.x, tid = threadIdx.x;
    const int i4 = tid >> 4, j4 = (tid & 15) * 4;            // T-phase mapping
    const int u  = tid & 511;
    const int i8 = u >> 3, j8 = (u & 7) * 8;                 // half-phase mapping

    if (tid < NCH) {
        float s = 0.f;
#pragma unroll
        for (int k = 0; k < GBLK; ++k) s += g_psum[b][k][tid];
        float m = s * (1.f / (float)HW);
        mean_s[tid] = m;
        g_mean[b][tid] = m;
    }
    __syncthreads();

    const float inv_d = 1.f / (float)(HW - 1);
    for (int e = tid; e < 4096; e += 1024) {
        float s = 0.f;
#pragma unroll
        for (int k = 0; k < GBLK; ++k) s += g_part[b][k][e];
        int i = e >> 6, j = e & 63;
        sZ[i * MS + j] = (s - (float)HW * mean_s[i] * mean_s[j]) * inv_d;
    }
    __syncthreads();

    if (tid < 64) {
        float s = 0.f;
        for (int j = 0; j < 64; ++j) s += fabsf(sZ[tid * MS + j]);
        sY[tid] = s;
    }
    __syncthreads();
    if (tid == 0) {
        float m = 0.f;
        for (int r = 0; r < 64; ++r) m = fmaxf(m, sY[r]);
        sT[0] = m;
    }
    __syncthreads();
    const float c = sT[0];
    const float inv_c = 1.f / c;
    __syncthreads();

    for (int e = tid; e < 4096; e += 1024) {
        int r = e >> 6, q = e & 63;
        float v = sZ[r * MS + q];
        sY[r * MS + q] = v * inv_c;
        sZ[r * MS + q] = (r == q) ? 1.f : 0.f;
    }
    __syncthreads();

    for (int it = 0; it < NS_ITERS; ++it) {
        // T = 1.5 I - 0.5 * Z*Y   (all 1024 threads, 4-wide)
        unsigned long long t2[2];
        mm64p4(sZ, sY, t2, i4, j4);
#pragma unroll
        for (int q = 0; q < 2; q++) {
            int j = j4 + 2 * q;
            sT[i4 * MS + j]     = ((i4 == j)     ? 1.5f : 0.f) - 0.5f * lo32(t2[q]);
            sT[i4 * MS + j + 1] = ((i4 == j + 1) ? 1.5f : 0.f) - 0.5f * hi32(t2[q]);
        }
        __syncthreads();

        // Y' = Y*T (tid<512), Z' = T*Z (tid>=512), concurrent
        unsigned long long r2[4];
        if (tid < 512) mm64p8(sY, sT, r2, i8, j8);
        else           mm64p8(sT, sZ, r2, i8, j8);
        __syncthreads();
        float* dst = (tid < 512) ? sY : sZ;
#pragma unroll
        for (int q = 0; q < 4; q++) {
            dst[i8 * MS + j8 + 2 * q]     = lo32(r2[q]);
            dst[i8 * MS + j8 + 2 * q + 1] = hi32(r2[q]);
        }
        __syncthreads();
    }

    const float sc = sqrtf(c), isc = rsqrtf(c);
    for (int e = tid; e < 4096; e += 1024) {
        int r = e >> 6, q = e & 63;
        g_half[b][e] = sY[r * MS + q] * sc;
        g_invh[b][e] = sZ[r * MS + q] * isc;
    }
}

// ============================================================================
// Kernel 3: A_b (row-major) + bias_b. grid BATCH, 512 threads.
// ============================================================================
__global__ void __launch_bounds__(512) comb_kernel(const int* __restrict__ perm,
                                                   const float* __restrict__ alpha) {
    __shared__ float sS[64 * MS], sTi[64 * MS], red[512];
    const int b = blockIdx.x, tid = threadIdx.x;
    const int pb = perm[b];
    const float al = alpha[b];
    const float oma = 1.f - al;

    for (int e = tid; e < 4096; e += 512) {
        int r = e >> 6, q = e & 63;
        sS [r * MS + q] = g_half[pb][e];
        sTi[r * MS + q] = g_invh[b][e];
    }
    __syncthreads();

    const int i = tid >> 3, j0 = (tid & 7) * 8;
    unsigned long long m2[4];
    mm64p8(sS, sTi, m2, i, j0);

    float m[8];
#pragma unroll
    for (int q = 0; q < 4; q++) { m[2 * q] = lo32(m2[q]); m[2 * q + 1] = hi32(m2[q]); }

    float pdot = 0.f;
#pragma unroll
    for (int q = 0; q < 8; q++) {
        int j = j0 + q;
        g_A[b][i * 64 + j] = ((i == j) ? al : 0.f) + oma * m[q];
        pdot += m[q] * g_mean[b][j];
    }
    red[tid] = pdot;
    __syncthreads();
    if (tid < 64) {
        float dot = 0.f;
#pragma unroll
        for (int t = 0; t < 8; t++) dot += red[tid * 8 + t];
        g_bias[b][tid] = oma * (g_mean[pb][tid] - dot);
    }
}

// ============================================================================
// Kernel 4: out = A*x + bias via mma.sync bf16 split (verified structure;
// packed bf16x2 cvt staging). grid (ABLKS, BATCH), 256 threads, 2 blk/SM.
// ============================================================================
#define SM_HX0  0
#define SM_HX1  18432
#define SM_LX0  36864
#define SM_LX1  55296
#define SM_AH   73728
#define SM_AL   82944
#define SM_BIAS 92160
#define APPLY_SMEM (SM_BIAS + 256)

__device__ __forceinline__ void stage_tile(unsigned short* hx, unsigned short* lx,
                                           const float4* __restrict__ src, int tid) {
#pragma unroll
    for (int r = 0; r < 8; ++r) {
        const int f = tid + 256 * r;
        const float4 v = src[f];
        const int px = f >> 4, k0 = (f & 15) * 4;
        __nv_bfloat162 h01 = __float22bfloat162_rn(make_float2(v.x, v.y));
        __nv_bfloat162 h23 = __float22bfloat162_rn(make_float2(v.z, v.w));
        float2 f01 = __bfloat1622float2(h01);
        float2 f23 = __bfloat1622float2(h23);
        __nv_bfloat162 l01 = __float22bfloat162_rn(make_float2(v.x - f01.x, v.y - f01.y));
        __nv_bfloat162 l23 = __float22bfloat162_rn(make_float2(v.z - f23.x, v.w - f23.y));
        uint2 hp, lp;
        hp.x = bf2bits(h01); hp.y = bf2bits(h23);
        lp.x = bf2bits(l01); lp.y = bf2bits(l23);
        *reinterpret_cast<uint2*>(hx + px * XROW + k0) = hp;
        *reinterpret_cast<uint2*>(lx + px * XROW + k0) = lp;
    }
}

__global__ void __launch_bounds__(256, 2) apply_mma_kernel(const float* __restrict__ x,
                                                           float* __restrict__ out) {
    extern __shared__ char smem[];
    unsigned short* HX[2] = {(unsigned short*)(smem + SM_HX0),
                             (unsigned short*)(smem + SM_HX1)};
    unsigned short* LX[2] = {(unsigned short*)(smem + SM_LX0),
                             (unsigned short*)(smem + SM_LX1)};
    unsigned short* AH = (unsigned short*)(smem + SM_AH);
    unsigned short* AL = (unsigned short*)(smem + SM_AL);
    float* sbias = (float*)(smem + SM_BIAS);

    const int tid = threadIdx.x;
    const int w = tid >> 5, lane = tid & 31;
    const int b = blockIdx.y, blk = blockIdx.x;

    for (int e = tid; e < 4096; e += 256) {
        const int c = e >> 6, k = e & 63;
        const float a = g_A[b][e];
        __nv_bfloat16 h = __float2bfloat16_rn(a);
        float rl = a - __bfloat162float(h);
        AH[c * AROW + k] = __bfloat16_as_ushort(h);
        AL[c * AROW + k] = __bfloat16_as_ushort(__float2bfloat16_rn(rl));
    }
    if (tid < 64) sbias[tid] = g_bias[b][tid];

    const float4* x4 = reinterpret_cast<const float4*>(x) +
                       ((size_t)b * HW + (size_t)blk * APB) * (NCH / 4);
    float* ob = out + ((size_t)b * HW + (size_t)blk * APB) * NCH;

    stage_tile(HX[0], LX[0], x4, tid);
    __syncthreads();

    const int pxb   = (w >> 1) * 32;
    const int nbase = (w & 1) * 32;
    uint32_t Bh[4][4][2], Bl[4][4][2];
    {
        const uint32_t ah_s = smem_u32(AH), al_s = smem_u32(AL);
        const int rown = nbase + (lane & 7) + ((lane >> 4) << 3);
        const int koff = ((lane >> 3) & 1) * 8;
#pragma unroll
        for (int ks = 0; ks < 4; ++ks)
#pragma unroll
            for (int ntp = 0; ntp < 2; ++ntp) {
                const uint32_t off =
                    (uint32_t)(((rown + ntp * 16) * AROW + ks * 16 + koff) * 2);
                uint32_t rh[4], rl[4];
                ldm4(rh, ah_s + off);
                ldm4(rl, al_s + off);
                Bh[ks][ntp * 2][0] = rh[0]; Bh[ks][ntp * 2][1] = rh[1];
                Bh[ks][ntp * 2 + 1][0] = rh[2]; Bh[ks][ntp * 2 + 1][1] = rh[3];
                Bl[ks][ntp * 2][0] = rl[0]; Bl[ks][ntp * 2][1] = rl[1];
                Bl[ks][ntp * 2 + 1][0] = rl[2]; Bl[ks][ntp * 2 + 1][1] = rl[3];
            }
    }

    float2 bv[4];
    {
        const int cpair = (lane & 3) * 2;
#pragma unroll
        for (int nt = 0; nt < 4; ++nt) {
            bv[nt].x = sbias[nbase + nt * 8 + cpair];
            bv[nt].y = sbias[nbase + nt * 8 + cpair + 1];
        }
    }

    const int xrow = (lane & 15);
    const int xkof = ((lane >> 4) << 3);

    for (int t = 0; t < NTIL; ++t) {
        const int cb = t & 1;

        if (t + 1 < NTIL)
            stage_tile(HX[cb ^ 1], LX[cb ^ 1], x4 + (size_t)(t + 1) * 2048, tid);

        const uint32_t hx_s = smem_u32(HX[cb]), lx_s = smem_u32(LX[cb]);

        float C[2][4][4];
#pragma unroll
        for (int mt = 0; mt < 2; ++mt)
#pragma unroll
            for (int nt = 0; nt < 4; ++nt)
#pragma unroll
                for (int q = 0; q < 4; ++q) C[mt][nt][q] = 0.f;

#pragma unroll
        for (int ks = 0; ks < 4; ++ks) {
            uint32_t ah[2][4], al[2][4];
#pragma unroll
            for (int mt = 0; mt < 2; ++mt) {
                const uint32_t off = (uint32_t)(
                    ((pxb + mt * 16 + xrow) * XROW + ks * 16 + xkof) * 2);
                ldm4(ah[mt], hx_s + off);
                ldm4(al[mt], lx_s + off);
            }
#pragma unroll
            for (int mt = 0; mt < 2; ++mt)
#pragma unroll
                for (int nt = 0; nt < 4; ++nt) {
                    mma_bf16(C[mt][nt], ah[mt], Bh[ks][nt][0], Bh[ks][nt][1]);
                    mma_bf16(C[mt][nt], al[mt], Bh[ks][nt][0], Bh[ks][nt][1]);
                    mma_bf16(C[mt][nt], ah[mt], Bl[ks][nt][0], Bl[ks][nt][1]);
                }
        }

        const int gr = lane >> 2, cpair = (lane & 3) * 2;
        const int pxg = t * ATL + pxb + gr;
#pragma unroll
        for (int mt = 0; mt < 2; ++mt) {
            float* row0 = ob + (size_t)(pxg + mt * 16) * NCH;
            float* row1 = row0 + 8 * NCH;
#pragma unroll
            for (int nt = 0; nt < 4; ++nt) {
                const int n = nbase + nt * 8 + cpair;
                *reinterpret_cast<float2*>(row0 + n) =
                    make_float2(C[mt][nt][0] + bv[nt].x, C[mt][nt][1] + bv[nt].y);
                *reinterpret_cast<float2*>(row1 + n) =
                    make_float2(C[mt][nt][2] + bv[nt].x, C[mt][nt][3] + bv[nt].y);
            }
        }
        __syncthreads();
    }
}

// ============================================================================
extern "C" void kernel_launch(void* const* d_in, const int* in_sizes, int n_in,
                              void* d_out, int out_size) {
    (void)in_sizes; (void)n_in; (void)out_size;
    const float* x     = (const float*)d_in[0];
    const int*   perm  = (const int*)d_in[1];
    const float* alpha = (const float*)d_in[2];
    float*       out   = (float*)d_out;

    const int ns_smem   = 3 * 64 * MS * (int)sizeof(float);   // 52224 B
    const int gram_smem = 2 * 18432;                          // 36864 B
    cudaFuncSetAttribute(ns_kernel, cudaFuncAttributeMaxDynamicSharedMemorySize, ns_smem);
    cudaFuncSetAttribute(apply_mma_kernel, cudaFuncAttributeMaxDynamicSharedMemorySize,
                         APPLY_SMEM);

    gram_mma_kernel<<<dim3(GBLK, BATCH), 256, gram_smem>>>(x);
    ns_kernel<<<BATCH, 1024, ns_smem>>>();
    comb_kernel<<<BATCH, 512>>>(perm, alpha);
    apply_mma_kernel<<<dim3(ABLKS, BATCH), 256, APPLY_SMEM>>>(x, out);
}